// round 5
// baseline (speedup 1.0000x reference)
#include <cuda_runtime.h>
#include <math.h>
#include <stdint.h>

// Problem constants
#define NTOK 8192
#define DIM  2048
#define FDIM 5632
#define NE   8
#define NASSIGN (NTOK * 2)
#define GU_N  (2 * FDIM)          // 11264: gate rows [0,F), up rows [F,2F)

// ---------------------------------------------------------------------------
// Scratch (device globals; no dynamic allocation allowed)
// ---------------------------------------------------------------------------
__device__ int   g_cnt[NE];
__device__ int   g_off[NE];
__device__ int   g_cursor[NE];
__device__ int   g_tok_eid[NASSIGN];
__device__ float g_tok_w[NASSIGN];
__device__ int   g_assign_slot[NASSIGN];   // assignment i -> slot
__device__ int   g_slot_token[NASSIGN];    // slot -> token
__device__ float g_probsum[NE];
__device__ float g_fraccnt[NE];
__device__ float g_gu[(size_t)NASSIGN * GU_N];   // 738 MB: raw gate/up outputs
__device__ float g_tmp[(size_t)NASSIGN * DIM];   // 134 MB: per-slot down output

// ---------------------------------------------------------------------------
// Helpers
// ---------------------------------------------------------------------------
__device__ __forceinline__ uint32_t f2tf32(float x) {
    uint32_t u;
    asm("cvt.rna.tf32.f32 %0, %1;" : "=r"(u) : "f"(x));
    return u;
}

__device__ __forceinline__ void mma_tf32(float c[4], const uint32_t a[4],
                                         uint32_t b0, uint32_t b1) {
    asm volatile(
        "mma.sync.aligned.m16n8k8.row.col.f32.tf32.tf32.f32 "
        "{%0,%1,%2,%3}, {%4,%5,%6,%7}, {%8,%9}, {%0,%1,%2,%3};"
        : "+f"(c[0]), "+f"(c[1]), "+f"(c[2]), "+f"(c[3])
        : "r"(a[0]), "r"(a[1]), "r"(a[2]), "r"(a[3]), "r"(b0), "r"(b1));
}

__device__ __forceinline__ float silu(float g) {
    return g / (1.f + __expf(-g));
}

// Smem layout (floats): A stages at s*4608, B stages at 9216 + s*4608.
// Row stride 36 floats: 16B-aligned uint4 stores, conflict-free fragment LDS.
#define STAGE_F 4608
#define B_BASE  9216
#define SMEM_BYTES (4 * STAGE_F * 4)   // 73728

// ---------------------------------------------------------------------------
// K0: reset per-launch accumulators
// ---------------------------------------------------------------------------
__global__ void reset_kernel() {
    int i = threadIdx.x;
    if (i < NE) { g_cnt[i] = 0; g_probsum[i] = 0.f; g_fraccnt[i] = 0.f; }
}

// ---------------------------------------------------------------------------
// K1: router — logits, softmax, top-2, counts, aux partials.  1 warp / token.
// ---------------------------------------------------------------------------
__global__ void __launch_bounds__(256) router_kernel(const float* __restrict__ x,
                                                     const float* __restrict__ rw) {
    __shared__ float s_prob[NE], s_frac[NE];
    int tid = threadIdx.x;
    if (tid < NE) { s_prob[tid] = 0.f; s_frac[tid] = 0.f; }
    __syncthreads();

    int lane = tid & 31;
    int tok  = blockIdx.x * 8 + (tid >> 5);

    float acc[NE];
#pragma unroll
    for (int e = 0; e < NE; e++) acc[e] = 0.f;

    const float* xr = x + (size_t)tok * DIM;
    for (int d = lane; d < DIM; d += 32) {
        float xv = xr[d];
#pragma unroll
        for (int e = 0; e < NE; e++) acc[e] += xv * rw[e * DIM + d];
    }
#pragma unroll
    for (int e = 0; e < NE; e++) {
#pragma unroll
        for (int o = 16; o > 0; o >>= 1)
            acc[e] += __shfl_xor_sync(0xffffffffu, acc[e], o);
    }

    if (lane == 0) {
        float mx = acc[0];
#pragma unroll
        for (int e = 1; e < NE; e++) mx = fmaxf(mx, acc[e]);
        float p[NE]; float s = 0.f;
#pragma unroll
        for (int e = 0; e < NE; e++) { p[e] = expf(acc[e] - mx); s += p[e]; }
        float inv = 1.f / s;
#pragma unroll
        for (int e = 0; e < NE; e++) p[e] *= inv;

        int e1 = 0;
#pragma unroll
        for (int e = 1; e < NE; e++) if (p[e] > p[e1]) e1 = e;
        int e2 = (e1 == 0) ? 1 : 0;
#pragma unroll
        for (int e = 0; e < NE; e++) if (e != e1 && p[e] > p[e2]) e2 = e;

        float wn = 1.f / (p[e1] + p[e2]);
        g_tok_eid[tok * 2]     = e1;
        g_tok_eid[tok * 2 + 1] = e2;
        g_tok_w[tok * 2]       = p[e1] * wn;
        g_tok_w[tok * 2 + 1]   = p[e2] * wn;
        atomicAdd(&g_cnt[e1], 1);
        atomicAdd(&g_cnt[e2], 1);
#pragma unroll
        for (int e = 0; e < NE; e++) atomicAdd(&s_prob[e], p[e]);
        atomicAdd(&s_frac[e1], 1.f);
        atomicAdd(&s_frac[e2], 1.f);
    }
    __syncthreads();
    if (tid < NE) {
        atomicAdd(&g_probsum[tid], s_prob[tid]);
        atomicAdd(&g_fraccnt[tid], s_frac[tid]);
    }
}

// ---------------------------------------------------------------------------
// K2: exclusive scan of counts
// ---------------------------------------------------------------------------
__global__ void scan_kernel() {
    int off = 0;
    for (int e = 0; e < NE; e++) {
        g_off[e] = off;
        g_cursor[e] = off;
        off += g_cnt[e];
    }
}

// ---------------------------------------------------------------------------
// K3: fill per-expert slot lists
// ---------------------------------------------------------------------------
__global__ void fill_kernel() {
    int i = blockIdx.x * blockDim.x + threadIdx.x;
    if (i < NASSIGN) {
        int e = g_tok_eid[i];
        int slot = atomicAdd(&g_cursor[e], 1);
        g_slot_token[slot] = i >> 1;
        g_assign_slot[i]   = slot;
    }
}

// ---------------------------------------------------------------------------
// K4: gateup GEMM — C[slot, 0:2F] = X_gathered @ [gate;up]^T   (raw, no silu)
//   CTA 128x128x32, 8 warps (4m x 2n), warp tile 32x64.
//   2-stage smem + register prefetch; one __syncthreads per K-slab.
// ---------------------------------------------------------------------------
__global__ void __launch_bounds__(256) gateup_kernel(const float* __restrict__ x,
                                                     const float* __restrict__ gate_w,
                                                     const float* __restrict__ up_w) {
    extern __shared__ float sm[];
    const int ITERS = DIM / 32;   // 64

    int e   = blockIdx.z;
    int cnt = g_cnt[e];
    int m0  = blockIdx.x * 128;
    if (m0 >= cnt) return;
    int n0  = blockIdx.y * 128;
    int off = g_off[e];

    int tid  = threadIdx.x;
    int lane = tid & 31;
    int w    = tid >> 5;
    int wm   = w & 3;           // 4 m-positions * 32 rows
    int wn   = w >> 2;          // 2 n-positions * 64 cols
    int gid  = lane >> 2;
    int tig  = lane & 3;

    // Loader: thread covers row ar (of both A and B tiles), 4 float4s.
    int ar = tid >> 1;
    int aq = (tid & 1) * 4;     // float4-quad base (k offset = aq*4 floats)

    const float* aptr = nullptr;
    if (m0 + ar < cnt)
        aptr = x + (size_t)g_slot_token[off + m0 + ar] * DIM + aq * 4;
    int ng = n0 + ar;
    const float* bptr = (ng < FDIM)
        ? gate_w + ((size_t)e * FDIM + ng) * DIM + aq * 4
        : up_w   + ((size_t)e * FDIM + (ng - FDIM)) * DIM + aq * 4;

    float4 ra[4], rb[4];

    auto load_t = [&](int t) {
        int k0 = t * 32;
        if (aptr) {
#pragma unroll
            for (int j = 0; j < 4; j++) ra[j] = *(const float4*)(aptr + k0 + j * 4);
        } else {
#pragma unroll
            for (int j = 0; j < 4; j++) ra[j] = make_float4(0.f, 0.f, 0.f, 0.f);
        }
#pragma unroll
        for (int j = 0; j < 4; j++) rb[j] = *(const float4*)(bptr + k0 + j * 4);
    };
    auto sts_t = [&](int s) {
        float* A = sm + s * STAGE_F;
        float* B = sm + B_BASE + s * STAGE_F;
#pragma unroll
        for (int j = 0; j < 4; j++) {
            *(uint4*)&A[ar * 36 + (aq + j) * 4] =
                make_uint4(f2tf32(ra[j].x), f2tf32(ra[j].y), f2tf32(ra[j].z), f2tf32(ra[j].w));
            *(uint4*)&B[ar * 36 + (aq + j) * 4] =
                make_uint4(f2tf32(rb[j].x), f2tf32(rb[j].y), f2tf32(rb[j].z), f2tf32(rb[j].w));
        }
    };

    float c[2][8][4];
#pragma unroll
    for (int mi = 0; mi < 2; mi++)
#pragma unroll
        for (int ni = 0; ni < 8; ni++)
#pragma unroll
            for (int q = 0; q < 4; q++) c[mi][ni][q] = 0.f;

    load_t(0); sts_t(0); load_t(1);
    __syncthreads();

#pragma unroll 1
    for (int i = 0; i < ITERS; i++) {
        int s = i & 1;
        if (i + 1 < ITERS) sts_t(s ^ 1);
        if (i + 2 < ITERS) load_t(i + 2);

        const float* A = sm + s * STAGE_F;
        const float* B = sm + B_BASE + s * STAGE_F;
#pragma unroll
        for (int kk = 0; kk < 32; kk += 8) {
            uint32_t a[2][4];
#pragma unroll
            for (int mi = 0; mi < 2; mi++) {
                int r = wm * 32 + mi * 16 + gid;
                a[mi][0] = *(const uint32_t*)&A[r * 36 + kk + tig];
                a[mi][1] = *(const uint32_t*)&A[(r + 8) * 36 + kk + tig];
                a[mi][2] = *(const uint32_t*)&A[r * 36 + kk + tig + 4];
                a[mi][3] = *(const uint32_t*)&A[(r + 8) * 36 + kk + tig + 4];
            }
#pragma unroll
            for (int ni = 0; ni < 8; ni++) {
                int cc = wn * 64 + ni * 8 + gid;
                uint32_t b0 = *(const uint32_t*)&B[cc * 36 + kk + tig];
                uint32_t b1 = *(const uint32_t*)&B[cc * 36 + kk + tig + 4];
#pragma unroll
                for (int mi = 0; mi < 2; mi++)
                    mma_tf32(c[mi][ni], a[mi], b0, b1);
            }
        }
        __syncthreads();
    }

    // Epilogue: raw stores to g_gu
#pragma unroll
    for (int mi = 0; mi < 2; mi++) {
#pragma unroll
        for (int ni = 0; ni < 8; ni++) {
            int col = n0 + wn * 64 + ni * 8 + 2 * tig;
            int r0  = m0 + wm * 32 + mi * 16 + gid;
            if (r0 < cnt) {
                float2* p = (float2*)&g_gu[(size_t)(off + r0) * GU_N + col];
                *p = make_float2(c[mi][ni][0], c[mi][ni][1]);
            }
            if (r0 + 8 < cnt) {
                float2* p = (float2*)&g_gu[(size_t)(off + r0 + 8) * GU_N + col];
                *p = make_float2(c[mi][ni][2], c[mi][ni][3]);
            }
        }
    }
}

// ---------------------------------------------------------------------------
// K5: down GEMM — A = silu(gate)*up computed in the load path from g_gu.
//   Same pipeline/tiling. Output unweighted to g_tmp.
// ---------------------------------------------------------------------------
__global__ void __launch_bounds__(256) down_kernel(const float* __restrict__ down_w) {
    extern __shared__ float sm[];
    const int ITERS = FDIM / 32;  // 176

    int e   = blockIdx.z;
    int cnt = g_cnt[e];
    int m0  = blockIdx.x * 128;
    if (m0 >= cnt) return;
    int n0  = blockIdx.y * 128;
    int off = g_off[e];

    int tid  = threadIdx.x;
    int lane = tid & 31;
    int w    = tid >> 5;
    int wm   = w & 3;
    int wn   = w >> 2;
    int gid  = lane >> 2;
    int tig  = lane & 3;

    int ar = tid >> 1;
    int aq = (tid & 1) * 4;

    const float* gptr = nullptr;
    if (m0 + ar < cnt)
        gptr = g_gu + (size_t)(off + m0 + ar) * GU_N + aq * 4;
    const float* bptr = down_w + ((size_t)e * DIM + n0 + ar) * FDIM + aq * 4;

    float4 ra[4], rb[4];

    auto load_t = [&](int t) {
        int k0 = t * 32;
        if (gptr) {
#pragma unroll
            for (int j = 0; j < 4; j++) {
                float4 gv = *(const float4*)(gptr + k0 + j * 4);
                float4 uv = *(const float4*)(gptr + FDIM + k0 + j * 4);
                ra[j].x = silu(gv.x) * uv.x;
                ra[j].y = silu(gv.y) * uv.y;
                ra[j].z = silu(gv.z) * uv.z;
                ra[j].w = silu(gv.w) * uv.w;
            }
        } else {
#pragma unroll
            for (int j = 0; j < 4; j++) ra[j] = make_float4(0.f, 0.f, 0.f, 0.f);
        }
#pragma unroll
        for (int j = 0; j < 4; j++) rb[j] = *(const float4*)(bptr + k0 + j * 4);
    };
    auto sts_t = [&](int s) {
        float* A = sm + s * STAGE_F;
        float* B = sm + B_BASE + s * STAGE_F;
#pragma unroll
        for (int j = 0; j < 4; j++) {
            *(uint4*)&A[ar * 36 + (aq + j) * 4] =
                make_uint4(f2tf32(ra[j].x), f2tf32(ra[j].y), f2tf32(ra[j].z), f2tf32(ra[j].w));
            *(uint4*)&B[ar * 36 + (aq + j) * 4] =
                make_uint4(f2tf32(rb[j].x), f2tf32(rb[j].y), f2tf32(rb[j].z), f2tf32(rb[j].w));
        }
    };

    float c[2][8][4];
#pragma unroll
    for (int mi = 0; mi < 2; mi++)
#pragma unroll
        for (int ni = 0; ni < 8; ni++)
#pragma unroll
            for (int q = 0; q < 4; q++) c[mi][ni][q] = 0.f;

    load_t(0); sts_t(0); load_t(1);
    __syncthreads();

#pragma unroll 1
    for (int i = 0; i < ITERS; i++) {
        int s = i & 1;
        if (i + 1 < ITERS) sts_t(s ^ 1);
        if (i + 2 < ITERS) load_t(i + 2);

        const float* A = sm + s * STAGE_F;
        const float* B = sm + B_BASE + s * STAGE_F;
#pragma unroll
        for (int kk = 0; kk < 32; kk += 8) {
            uint32_t a[2][4];
#pragma unroll
            for (int mi = 0; mi < 2; mi++) {
                int r = wm * 32 + mi * 16 + gid;
                a[mi][0] = *(const uint32_t*)&A[r * 36 + kk + tig];
                a[mi][1] = *(const uint32_t*)&A[(r + 8) * 36 + kk + tig];
                a[mi][2] = *(const uint32_t*)&A[r * 36 + kk + tig + 4];
                a[mi][3] = *(const uint32_t*)&A[(r + 8) * 36 + kk + tig + 4];
            }
#pragma unroll
            for (int ni = 0; ni < 8; ni++) {
                int cc = wn * 64 + ni * 8 + gid;
                uint32_t b0 = *(const uint32_t*)&B[cc * 36 + kk + tig];
                uint32_t b1 = *(const uint32_t*)&B[cc * 36 + kk + tig + 4];
#pragma unroll
                for (int mi = 0; mi < 2; mi++)
                    mma_tf32(c[mi][ni], a[mi], b0, b1);
            }
        }
        __syncthreads();
    }

#pragma unroll
    for (int mi = 0; mi < 2; mi++) {
#pragma unroll
        for (int ni = 0; ni < 8; ni++) {
            int col = n0 + wn * 64 + ni * 8 + 2 * tig;
            int r0  = m0 + wm * 32 + mi * 16 + gid;
            if (r0 < cnt) {
                float2* p = (float2*)&g_tmp[(size_t)(off + r0) * DIM + col];
                *p = make_float2(c[mi][ni][0], c[mi][ni][1]);
            }
            if (r0 + 8 < cnt) {
                float2* p = (float2*)&g_tmp[(size_t)(off + r0 + 8) * DIM + col];
                *p = make_float2(c[mi][ni][2], c[mi][ni][3]);
            }
        }
    }
}

// ---------------------------------------------------------------------------
// K6: combine — out[t] = w0*tmp[slot0] + w1*tmp[slot1]  (coalesced, no atomics)
// ---------------------------------------------------------------------------
__global__ void __launch_bounds__(256) combine_kernel(float* __restrict__ out) {
    int t = blockIdx.x;
    int d = blockIdx.y * 1024 + threadIdx.x * 4;
    int s0 = g_assign_slot[2 * t];
    int s1 = g_assign_slot[2 * t + 1];
    float w0 = g_tok_w[2 * t];
    float w1 = g_tok_w[2 * t + 1];
    float4 a = *(const float4*)(g_tmp + (size_t)s0 * DIM + d);
    float4 b = *(const float4*)(g_tmp + (size_t)s1 * DIM + d);
    float4 o;
    o.x = w0 * a.x + w1 * b.x;
    o.y = w0 * a.y + w1 * b.y;
    o.z = w0 * a.z + w1 * b.z;
    o.w = w0 * a.w + w1 * b.w;
    *(float4*)(out + (size_t)t * DIM + d) = o;
}

// ---------------------------------------------------------------------------
// K7: aux loss scalar
// ---------------------------------------------------------------------------
__global__ void aux_kernel(float* o) {
    float a = 0.f;
    for (int e = 0; e < NE; e++)
        a += (g_probsum[e] / (float)NTOK) * (g_fraccnt[e] / (float)NTOK);
    *o = (float)NE * a;
}

// ---------------------------------------------------------------------------
// Entry
// ---------------------------------------------------------------------------
extern "C" void kernel_launch(void* const* d_in, const int* in_sizes, int n_in,
                              void* d_out, int out_size) {
    const float* x  = (const float*)d_in[0];   // [B,T,D]
    const float* rw = (const float*)d_in[1];   // [E,D]
    const float* gw = (const float*)d_in[2];   // [E,F,D]
    const float* uw = (const float*)d_in[3];   // [E,F,D]
    const float* dw = (const float*)d_in[4];   // [E,D,F]
    float* out = (float*)d_out;

    cudaFuncSetAttribute(gateup_kernel, cudaFuncAttributeMaxDynamicSharedMemorySize,
                         SMEM_BYTES);
    cudaFuncSetAttribute(down_kernel, cudaFuncAttributeMaxDynamicSharedMemorySize,
                         SMEM_BYTES);

    reset_kernel<<<1, 32>>>();
    router_kernel<<<NTOK / 8, 256>>>(x, rw);
    scan_kernel<<<1, 1>>>();
    fill_kernel<<<NASSIGN / 256, 256>>>();
    gateup_kernel<<<dim3(128, GU_N / 128, NE), 256, SMEM_BYTES>>>(x, gw, uw);
    down_kernel<<<dim3(128, DIM / 128, NE), 256, SMEM_BYTES>>>(dw);
    combine_kernel<<<dim3(NTOK, 2), 256>>>(out);
    if (out_size > NTOK * DIM)
        aux_kernel<<<1, 1>>>(out + (size_t)NTOK * DIM);
}

// round 6
// speedup vs baseline: 1.1190x; 1.1190x over previous
#include <cuda_runtime.h>
#include <math.h>
#include <stdint.h>

// Problem constants
#define NTOK 8192
#define DIM  2048
#define FDIM 5632
#define NE   8
#define NASSIGN (NTOK * 2)

// ---------------------------------------------------------------------------
// Scratch (device globals; no dynamic allocation allowed)
// ---------------------------------------------------------------------------
__device__ int   g_cnt[NE];
__device__ int   g_off[NE];
__device__ int   g_cursor[NE];
__device__ int   g_tok_eid[NASSIGN];
__device__ float g_tok_w[NASSIGN];
__device__ int   g_assign_slot[NASSIGN];
__device__ int   g_slot_token[NASSIGN];
__device__ float g_probsum[NE];
__device__ float g_fraccnt[NE];

__device__ float g_xr [(size_t)NTOK * DIM];        //  67 MB: tf32-rounded x
__device__ float g_gwr[(size_t)NE * FDIM * DIM];   // 369 MB: rounded gate_w
__device__ float g_uwr[(size_t)NE * FDIM * DIM];   // 369 MB: rounded up_w
__device__ float g_dwr[(size_t)NE * DIM * FDIM];   // 369 MB: rounded down_w
__device__ float g_hbuf[(size_t)NASSIGN * FDIM];   // 369 MB: rounded h
__device__ float g_tmp[(size_t)NASSIGN * DIM];     // 134 MB: per-slot down out

// ---------------------------------------------------------------------------
// Helpers
// ---------------------------------------------------------------------------
__device__ __forceinline__ uint32_t f2tf32(float x) {
    uint32_t u;
    asm("cvt.rna.tf32.f32 %0, %1;" : "=r"(u) : "f"(x));
    return u;
}
__device__ __forceinline__ float roundtf(float x) {
    return __uint_as_float(f2tf32(x));
}

__device__ __forceinline__ void mma_tf32(float c[4], const uint32_t a[4],
                                         uint32_t b0, uint32_t b1) {
    asm volatile(
        "mma.sync.aligned.m16n8k8.row.col.f32.tf32.tf32.f32 "
        "{%0,%1,%2,%3}, {%4,%5,%6,%7}, {%8,%9}, {%0,%1,%2,%3};"
        : "+f"(c[0]), "+f"(c[1]), "+f"(c[2]), "+f"(c[3])
        : "r"(a[0]), "r"(a[1]), "r"(a[2]), "r"(a[3]), "r"(b0), "r"(b1));
}

__device__ __forceinline__ float silu(float g) {
    return g / (1.f + __expf(-g));
}

__device__ __forceinline__ uint32_t smem_u32(const void* p) {
    uint32_t a;
    asm("{ .reg .u64 t; cvta.to.shared.u64 t, %1; cvt.u32.u64 %0, t; }"
        : "=r"(a) : "l"(p));
    return a;
}

#define CP_ASYNC16(sa, gp) \
    asm volatile("cp.async.cg.shared.global [%0], [%1], 16;" :: "r"(sa), "l"(gp))
#define CP_COMMIT() asm volatile("cp.async.commit_group;" ::: "memory")
#define CP_WAIT1()  asm volatile("cp.async.wait_group 1;" ::: "memory")

// Smem: per stage A 128x36 floats (18432 B), B 128x36 floats; 3 stages.
// Row stride 36 floats = 144 B (16B-aligned; conflict-free fragment LDS).
#define ROWF     36
#define STAGE_F  (128 * ROWF)                 // 4608 floats
#define STAGE_B  (STAGE_F * 4)                // 18432 bytes
#define B_BASE_F (3 * STAGE_F)                // 13824 floats
#define B_BASE_B (3 * STAGE_B)                // 55296 bytes
#define SMEM_BYTES (6 * STAGE_B)              // 110592 bytes

// ---------------------------------------------------------------------------
// K0: reset
// ---------------------------------------------------------------------------
__global__ void reset_kernel() {
    int i = threadIdx.x;
    if (i < NE) { g_cnt[i] = 0; g_probsum[i] = 0.f; g_fraccnt[i] = 0.f; }
}

// ---------------------------------------------------------------------------
// K0b: elementwise tf32 RNA rounding (float4 grid-stride)
// ---------------------------------------------------------------------------
__global__ void __launch_bounds__(256) round_kernel(const float* __restrict__ src,
                                                    float* __restrict__ dst, int n4) {
    int i = blockIdx.x * blockDim.x + threadIdx.x;
    int stride = gridDim.x * blockDim.x;
    for (; i < n4; i += stride) {
        float4 v = ((const float4*)src)[i];
        v.x = roundtf(v.x); v.y = roundtf(v.y);
        v.z = roundtf(v.z); v.w = roundtf(v.w);
        ((float4*)dst)[i] = v;
    }
}

// ---------------------------------------------------------------------------
// K1: router — 1 warp/token
// ---------------------------------------------------------------------------
__global__ void __launch_bounds__(256) router_kernel(const float* __restrict__ x,
                                                     const float* __restrict__ rw) {
    __shared__ float s_prob[NE], s_frac[NE];
    int tid = threadIdx.x;
    if (tid < NE) { s_prob[tid] = 0.f; s_frac[tid] = 0.f; }
    __syncthreads();

    int lane = tid & 31;
    int tok  = blockIdx.x * 8 + (tid >> 5);

    float acc[NE];
#pragma unroll
    for (int e = 0; e < NE; e++) acc[e] = 0.f;

    const float* xr = x + (size_t)tok * DIM;
    for (int d = lane; d < DIM; d += 32) {
        float xv = xr[d];
#pragma unroll
        for (int e = 0; e < NE; e++) acc[e] += xv * rw[e * DIM + d];
    }
#pragma unroll
    for (int e = 0; e < NE; e++) {
#pragma unroll
        for (int o = 16; o > 0; o >>= 1)
            acc[e] += __shfl_xor_sync(0xffffffffu, acc[e], o);
    }

    if (lane == 0) {
        float mx = acc[0];
#pragma unroll
        for (int e = 1; e < NE; e++) mx = fmaxf(mx, acc[e]);
        float p[NE]; float s = 0.f;
#pragma unroll
        for (int e = 0; e < NE; e++) { p[e] = expf(acc[e] - mx); s += p[e]; }
        float inv = 1.f / s;
#pragma unroll
        for (int e = 0; e < NE; e++) p[e] *= inv;

        int e1 = 0;
#pragma unroll
        for (int e = 1; e < NE; e++) if (p[e] > p[e1]) e1 = e;
        int e2 = (e1 == 0) ? 1 : 0;
#pragma unroll
        for (int e = 0; e < NE; e++) if (e != e1 && p[e] > p[e2]) e2 = e;

        float wn = 1.f / (p[e1] + p[e2]);
        g_tok_eid[tok * 2]     = e1;
        g_tok_eid[tok * 2 + 1] = e2;
        g_tok_w[tok * 2]       = p[e1] * wn;
        g_tok_w[tok * 2 + 1]   = p[e2] * wn;
        atomicAdd(&g_cnt[e1], 1);
        atomicAdd(&g_cnt[e2], 1);
#pragma unroll
        for (int e = 0; e < NE; e++) atomicAdd(&s_prob[e], p[e]);
        atomicAdd(&s_frac[e1], 1.f);
        atomicAdd(&s_frac[e2], 1.f);
    }
    __syncthreads();
    if (tid < NE) {
        atomicAdd(&g_probsum[tid], s_prob[tid]);
        atomicAdd(&g_fraccnt[tid], s_frac[tid]);
    }
}

// ---------------------------------------------------------------------------
// K2/K3: scan + fill
// ---------------------------------------------------------------------------
__global__ void scan_kernel() {
    int off = 0;
    for (int e = 0; e < NE; e++) { g_off[e] = off; g_cursor[e] = off; off += g_cnt[e]; }
}

__global__ void fill_kernel() {
    int i = blockIdx.x * blockDim.x + threadIdx.x;
    if (i < NASSIGN) {
        int e = g_tok_eid[i];
        int slot = atomicAdd(&g_cursor[e], 1);
        g_slot_token[slot] = i >> 1;
        g_assign_slot[i]   = slot;
    }
}

// ---------------------------------------------------------------------------
// K4: fused gate/up GEMM, cp.async 3-stage pipeline.
//   CTA 128 x (64 gate | 64 up) x 32.  B tile rows 0..63 gate, 64..127 up.
//   8 warps = 4m x 2n; warp computes 32 rows x 32 cols of BOTH matrices.
//   Epilogue: h = round_tf32(silu(g)*u) -> g_hbuf.
// ---------------------------------------------------------------------------
__global__ void __launch_bounds__(256, 2) gateup_kernel() {
    extern __shared__ float sm[];
    const int ITERS = DIM / 32;   // 64

    int e   = blockIdx.z;
    int cnt = g_cnt[e];
    int m0  = blockIdx.x * 128;
    if (m0 >= cnt) return;
    int n0  = blockIdx.y * 64;
    int off = g_off[e];

    int tid  = threadIdx.x;
    int lane = tid & 31;
    int w    = tid >> 5;
    int wm   = w & 3;           // 4 m-positions * 32 rows
    int wn   = w >> 2;          // 2 n-positions * 32 cols
    int gid  = lane >> 2;
    int tig  = lane & 3;

    // Loader: thread -> row (tid>>1) of A and of B, half-row (tid&1)*16 floats.
    int lrow = tid >> 1;
    int lhf  = (tid & 1) * 16;

    int sidx = off + m0 + lrow;
    if (sidx > NASSIGN - 1) sidx = NASSIGN - 1;
    const float* aptr = g_xr + (size_t)g_slot_token[sidx] * DIM + lhf;
    const float* bptr = (lrow < 64)
        ? g_gwr + ((size_t)e * FDIM + n0 + lrow) * DIM + lhf
        : g_uwr + ((size_t)e * FDIM + n0 + (lrow - 64)) * DIM + lhf;

    uint32_t sb = smem_u32(sm);
    uint32_t sa_off = sb + (uint32_t)(lrow * 144 + (tid & 1) * 64);
    uint32_t sbf_off = sa_off + B_BASE_B;

    auto issue = [&](int t, int s) {
        uint32_t sa = sa_off + s * STAGE_B;
        uint32_t sbb = sbf_off + s * STAGE_B;
        const float* ga = aptr + t * 32;
        const float* gb = bptr + t * 32;
#pragma unroll
        for (int j = 0; j < 4; j++) CP_ASYNC16(sa + j * 16, ga + j * 4);
#pragma unroll
        for (int j = 0; j < 4; j++) CP_ASYNC16(sbb + j * 16, gb + j * 4);
        CP_COMMIT();
    };

    float cg[2][4][4], cu[2][4][4];
#pragma unroll
    for (int mi = 0; mi < 2; mi++)
#pragma unroll
        for (int ni = 0; ni < 4; ni++)
#pragma unroll
            for (int q = 0; q < 4; q++) { cg[mi][ni][q] = 0.f; cu[mi][ni][q] = 0.f; }

    issue(0, 0);
    issue(1, 1);

#pragma unroll 1
    for (int i = 0; i < ITERS; i++) {
        CP_WAIT1();
        __syncthreads();
        if (i + 2 < ITERS) issue(i + 2, (i + 2) % 3); else CP_COMMIT();

        const float* A = sm + (i % 3) * STAGE_F;
        const float* B = sm + B_BASE_F + (i % 3) * STAGE_F;
#pragma unroll
        for (int kk = 0; kk < 32; kk += 8) {
            uint32_t a[2][4];
#pragma unroll
            for (int mi = 0; mi < 2; mi++) {
                int r = wm * 32 + mi * 16 + gid;
                a[mi][0] = *(const uint32_t*)&A[r * ROWF + kk + tig];
                a[mi][1] = *(const uint32_t*)&A[(r + 8) * ROWF + kk + tig];
                a[mi][2] = *(const uint32_t*)&A[r * ROWF + kk + tig + 4];
                a[mi][3] = *(const uint32_t*)&A[(r + 8) * ROWF + kk + tig + 4];
            }
#pragma unroll
            for (int ni = 0; ni < 4; ni++) {
                int cc = wn * 32 + ni * 8 + gid;
                uint32_t bg0 = *(const uint32_t*)&B[cc * ROWF + kk + tig];
                uint32_t bg1 = *(const uint32_t*)&B[cc * ROWF + kk + tig + 4];
                uint32_t bu0 = *(const uint32_t*)&B[(cc + 64) * ROWF + kk + tig];
                uint32_t bu1 = *(const uint32_t*)&B[(cc + 64) * ROWF + kk + tig + 4];
#pragma unroll
                for (int mi = 0; mi < 2; mi++) {
                    mma_tf32(cg[mi][ni], a[mi], bg0, bg1);
                    mma_tf32(cu[mi][ni], a[mi], bu0, bu1);
                }
            }
        }
        __syncthreads();
    }

    // Epilogue: h = round(silu(g) * u)
#pragma unroll
    for (int mi = 0; mi < 2; mi++) {
#pragma unroll
        for (int ni = 0; ni < 4; ni++) {
            int col = n0 + wn * 32 + ni * 8 + 2 * tig;
            int r0  = m0 + wm * 32 + mi * 16 + gid;
            if (r0 < cnt) {
                float h0 = roundtf(silu(cg[mi][ni][0]) * cu[mi][ni][0]);
                float h1 = roundtf(silu(cg[mi][ni][1]) * cu[mi][ni][1]);
                *(float2*)&g_hbuf[(size_t)(off + r0) * FDIM + col] = make_float2(h0, h1);
            }
            if (r0 + 8 < cnt) {
                float h2 = roundtf(silu(cg[mi][ni][2]) * cu[mi][ni][2]);
                float h3 = roundtf(silu(cg[mi][ni][3]) * cu[mi][ni][3]);
                *(float2*)&g_hbuf[(size_t)(off + r0 + 8) * FDIM + col] = make_float2(h2, h3);
            }
        }
    }
}

// ---------------------------------------------------------------------------
// K5: down GEMM, cp.async 3-stage pipeline.  CTA 128x128x32, warp 32x64.
// ---------------------------------------------------------------------------
__global__ void __launch_bounds__(256, 2) down_kernel() {
    extern __shared__ float sm[];
    const int ITERS = FDIM / 32;  // 176

    int e   = blockIdx.z;
    int cnt = g_cnt[e];
    int m0  = blockIdx.x * 128;
    if (m0 >= cnt) return;
    int n0  = blockIdx.y * 128;
    int off = g_off[e];

    int tid  = threadIdx.x;
    int lane = tid & 31;
    int w    = tid >> 5;
    int wm   = w & 3;
    int wn   = w >> 2;          // 2 n-positions * 64 cols
    int gid  = lane >> 2;
    int tig  = lane & 3;

    int lrow = tid >> 1;
    int lhf  = (tid & 1) * 16;

    int sidx = off + m0 + lrow;
    if (sidx > NASSIGN - 1) sidx = NASSIGN - 1;
    const float* aptr = g_hbuf + (size_t)sidx * FDIM + lhf;
    const float* bptr = g_dwr + ((size_t)e * DIM + n0 + lrow) * FDIM + lhf;

    uint32_t sb = smem_u32(sm);
    uint32_t sa_off = sb + (uint32_t)(lrow * 144 + (tid & 1) * 64);
    uint32_t sbf_off = sa_off + B_BASE_B;

    auto issue = [&](int t, int s) {
        uint32_t sa = sa_off + s * STAGE_B;
        uint32_t sbb = sbf_off + s * STAGE_B;
        const float* ga = aptr + t * 32;
        const float* gb = bptr + t * 32;
#pragma unroll
        for (int j = 0; j < 4; j++) CP_ASYNC16(sa + j * 16, ga + j * 4);
#pragma unroll
        for (int j = 0; j < 4; j++) CP_ASYNC16(sbb + j * 16, gb + j * 4);
        CP_COMMIT();
    };

    float c[2][8][4];
#pragma unroll
    for (int mi = 0; mi < 2; mi++)
#pragma unroll
        for (int ni = 0; ni < 8; ni++)
#pragma unroll
            for (int q = 0; q < 4; q++) c[mi][ni][q] = 0.f;

    issue(0, 0);
    issue(1, 1);

#pragma unroll 1
    for (int i = 0; i < ITERS; i++) {
        CP_WAIT1();
        __syncthreads();
        if (i + 2 < ITERS) issue(i + 2, (i + 2) % 3); else CP_COMMIT();

        const float* A = sm + (i % 3) * STAGE_F;
        const float* B = sm + B_BASE_F + (i % 3) * STAGE_F;
#pragma unroll
        for (int kk = 0; kk < 32; kk += 8) {
            uint32_t a[2][4];
#pragma unroll
            for (int mi = 0; mi < 2; mi++) {
                int r = wm * 32 + mi * 16 + gid;
                a[mi][0] = *(const uint32_t*)&A[r * ROWF + kk + tig];
                a[mi][1] = *(const uint32_t*)&A[(r + 8) * ROWF + kk + tig];
                a[mi][2] = *(const uint32_t*)&A[r * ROWF + kk + tig + 4];
                a[mi][3] = *(const uint32_t*)&A[(r + 8) * ROWF + kk + tig + 4];
            }
#pragma unroll
            for (int ni = 0; ni < 8; ni++) {
                int cc = wn * 64 + ni * 8 + gid;
                uint32_t b0 = *(const uint32_t*)&B[cc * ROWF + kk + tig];
                uint32_t b1 = *(const uint32_t*)&B[cc * ROWF + kk + tig + 4];
#pragma unroll
                for (int mi = 0; mi < 2; mi++)
                    mma_tf32(c[mi][ni], a[mi], b0, b1);
            }
        }
        __syncthreads();
    }

#pragma unroll
    for (int mi = 0; mi < 2; mi++) {
#pragma unroll
        for (int ni = 0; ni < 8; ni++) {
            int col = n0 + wn * 64 + ni * 8 + 2 * tig;
            int r0  = m0 + wm * 32 + mi * 16 + gid;
            if (r0 < cnt)
                *(float2*)&g_tmp[(size_t)(off + r0) * DIM + col] =
                    make_float2(c[mi][ni][0], c[mi][ni][1]);
            if (r0 + 8 < cnt)
                *(float2*)&g_tmp[(size_t)(off + r0 + 8) * DIM + col] =
                    make_float2(c[mi][ni][2], c[mi][ni][3]);
        }
    }
}

// ---------------------------------------------------------------------------
// K6: combine — out[t] = w0*tmp[slot0] + w1*tmp[slot1]
// ---------------------------------------------------------------------------
__global__ void __launch_bounds__(256) combine_kernel(float* __restrict__ out) {
    int t = blockIdx.x;
    int d = blockIdx.y * 1024 + threadIdx.x * 4;
    int s0 = g_assign_slot[2 * t];
    int s1 = g_assign_slot[2 * t + 1];
    float w0 = g_tok_w[2 * t];
    float w1 = g_tok_w[2 * t + 1];
    float4 a = *(const float4*)(g_tmp + (size_t)s0 * DIM + d);
    float4 b = *(const float4*)(g_tmp + (size_t)s1 * DIM + d);
    float4 o;
    o.x = w0 * a.x + w1 * b.x;
    o.y = w0 * a.y + w1 * b.y;
    o.z = w0 * a.z + w1 * b.z;
    o.w = w0 * a.w + w1 * b.w;
    *(float4*)(out + (size_t)t * DIM + d) = o;
}

// ---------------------------------------------------------------------------
// K7: aux loss scalar
// ---------------------------------------------------------------------------
__global__ void aux_kernel(float* o) {
    float a = 0.f;
    for (int e = 0; e < NE; e++)
        a += (g_probsum[e] / (float)NTOK) * (g_fraccnt[e] / (float)NTOK);
    *o = (float)NE * a;
}

// ---------------------------------------------------------------------------
// Entry
// ---------------------------------------------------------------------------
extern "C" void kernel_launch(void* const* d_in, const int* in_sizes, int n_in,
                              void* d_out, int out_size) {
    const float* x  = (const float*)d_in[0];   // [B,T,D]
    const float* rw = (const float*)d_in[1];   // [E,D]
    const float* gw = (const float*)d_in[2];   // [E,F,D]
    const float* uw = (const float*)d_in[3];   // [E,F,D]
    const float* dw = (const float*)d_in[4];   // [E,D,F]
    float* out = (float*)d_out;

    cudaFuncSetAttribute(gateup_kernel, cudaFuncAttributeMaxDynamicSharedMemorySize,
                         SMEM_BYTES);
    cudaFuncSetAttribute(down_kernel, cudaFuncAttributeMaxDynamicSharedMemorySize,
                         SMEM_BYTES);

    reset_kernel<<<1, 32>>>();
    router_kernel<<<NTOK / 8, 256>>>(x, rw);
    scan_kernel<<<1, 1>>>();
    fill_kernel<<<NASSIGN / 256, 256>>>();

    // Pre-round all GEMM operands to tf32 (RNA) so mainloops are pure cp.async.
    float* gwr; cudaGetSymbolAddress((void**)&gwr, g_gwr);
    float* uwr; cudaGetSymbolAddress((void**)&uwr, g_uwr);
    float* dwr; cudaGetSymbolAddress((void**)&dwr, g_dwr);
    float* xr;  cudaGetSymbolAddress((void**)&xr,  g_xr);
    const int WN4 = (NE * FDIM * DIM) / 4;     // 23,068,672
    const int XN4 = (NTOK * DIM) / 4;          //  4,194,304
    round_kernel<<<2048, 256>>>(gw, gwr, WN4);
    round_kernel<<<2048, 256>>>(uw, uwr, WN4);
    round_kernel<<<2048, 256>>>(dw, dwr, WN4);
    round_kernel<<<2048, 256>>>(x,  xr,  XN4);

    gateup_kernel<<<dim3(64, FDIM / 64, NE), 256, SMEM_BYTES>>>();
    down_kernel<<<dim3(64, DIM / 128, NE), 256, SMEM_BYTES>>>();
    combine_kernel<<<dim3(NTOK, 2), 256>>>(out);
    if (out_size > NTOK * DIM)
        aux_kernel<<<1, 1>>>(out + (size_t)NTOK * DIM);
}

// round 7
// speedup vs baseline: 2.1564x; 1.9270x over previous
#include <cuda_runtime.h>
#include <cuda_fp16.h>
#include <math.h>
#include <stdint.h>

// Problem constants
#define NTOK 8192
#define DIM  2048
#define FDIM 5632
#define NE   8
#define NASSIGN (NTOK * 2)

// ---------------------------------------------------------------------------
// Scratch (device globals; no dynamic allocation allowed)
// ---------------------------------------------------------------------------
__device__ int   g_cnt[NE];
__device__ int   g_off[NE];
__device__ int   g_cursor[NE];
__device__ int   g_tok_eid[NASSIGN];
__device__ float g_tok_w[NASSIGN];
__device__ int   g_assign_slot[NASSIGN];
__device__ int   g_slot_token[NASSIGN];
__device__ float g_probsum[NE];
__device__ float g_fraccnt[NE];

__device__ __half g_xh [(size_t)NTOK * DIM];        //  34 MB: fp16 x
__device__ __half g_gwh[(size_t)NE * FDIM * DIM];   // 185 MB: fp16 gate_w
__device__ __half g_uwh[(size_t)NE * FDIM * DIM];   // 185 MB: fp16 up_w
__device__ __half g_dwh[(size_t)NE * DIM * FDIM];   // 185 MB: fp16 down_w
__device__ __half g_hh [(size_t)NASSIGN * FDIM];    // 185 MB: fp16 h
__device__ float  g_tmp[(size_t)NASSIGN * DIM];     // 134 MB: per-slot down out

// ---------------------------------------------------------------------------
// Helpers
// ---------------------------------------------------------------------------
__device__ __forceinline__ void mma_f16(float c[4], const uint32_t a[4],
                                        uint32_t b0, uint32_t b1) {
    asm volatile(
        "mma.sync.aligned.m16n8k16.row.col.f32.f16.f16.f32 "
        "{%0,%1,%2,%3}, {%4,%5,%6,%7}, {%8,%9}, {%0,%1,%2,%3};"
        : "+f"(c[0]), "+f"(c[1]), "+f"(c[2]), "+f"(c[3])
        : "r"(a[0]), "r"(a[1]), "r"(a[2]), "r"(a[3]), "r"(b0), "r"(b1));
}

__device__ __forceinline__ float silu(float g) {
    return g / (1.f + __expf(-g));
}

__device__ __forceinline__ uint32_t smem_u32(const void* p) {
    uint32_t a;
    asm("{ .reg .u64 t; cvta.to.shared.u64 t, %1; cvt.u32.u64 %0, t; }"
        : "=r"(a) : "l"(p));
    return a;
}

#define CP_ASYNC16(sa, gp) \
    asm volatile("cp.async.cg.shared.global [%0], [%1], 16;" :: "r"(sa), "l"(gp))
#define CP_COMMIT() asm volatile("cp.async.commit_group;" ::: "memory")
#define CP_WAIT1()  asm volatile("cp.async.wait_group 1;" ::: "memory")

// Smem: K-slab = 64 halves (128B) per row + 16B pad -> 144B row stride.
// Per stage: A 128 rows, B 128 rows. 3 stages.
#define ROWH      72                          // halves per row (incl pad)
#define STAGE_H   (128 * ROWH)                // 9216 halves
#define STAGE_B2  (STAGE_H * 2)               // 18432 bytes
#define B_BASE_H  (3 * STAGE_H)               // 27648 halves
#define B_BASE_B2 (3 * STAGE_B2)              // 55296 bytes
#define SMEM_BYTES (6 * STAGE_B2)             // 110592 bytes

// ---------------------------------------------------------------------------
// K0: reset
// ---------------------------------------------------------------------------
__global__ void reset_kernel() {
    int i = threadIdx.x;
    if (i < NE) { g_cnt[i] = 0; g_probsum[i] = 0.f; g_fraccnt[i] = 0.f; }
}

// ---------------------------------------------------------------------------
// K0b: fp32 -> fp16 conversion (float4 -> half4, grid-stride)
// ---------------------------------------------------------------------------
__global__ void __launch_bounds__(256) cvt_kernel(const float* __restrict__ src,
                                                  __half* __restrict__ dst, int n4) {
    int i = blockIdx.x * blockDim.x + threadIdx.x;
    int stride = gridDim.x * blockDim.x;
    for (; i < n4; i += stride) {
        float4 v = ((const float4*)src)[i];
        __half2 h0 = __floats2half2_rn(v.x, v.y);
        __half2 h1 = __floats2half2_rn(v.z, v.w);
        uint2 u;
        u.x = *(const uint32_t*)&h0;
        u.y = *(const uint32_t*)&h1;
        ((uint2*)dst)[i] = u;
    }
}

// ---------------------------------------------------------------------------
// K1: router — 1 warp/token (fp32, exact)
// ---------------------------------------------------------------------------
__global__ void __launch_bounds__(256) router_kernel(const float* __restrict__ x,
                                                     const float* __restrict__ rw) {
    __shared__ float s_prob[NE], s_frac[NE];
    int tid = threadIdx.x;
    if (tid < NE) { s_prob[tid] = 0.f; s_frac[tid] = 0.f; }
    __syncthreads();

    int lane = tid & 31;
    int tok  = blockIdx.x * 8 + (tid >> 5);

    float acc[NE];
#pragma unroll
    for (int e = 0; e < NE; e++) acc[e] = 0.f;

    const float* xr = x + (size_t)tok * DIM;
    for (int d = lane; d < DIM; d += 32) {
        float xv = xr[d];
#pragma unroll
        for (int e = 0; e < NE; e++) acc[e] += xv * rw[e * DIM + d];
    }
#pragma unroll
    for (int e = 0; e < NE; e++) {
#pragma unroll
        for (int o = 16; o > 0; o >>= 1)
            acc[e] += __shfl_xor_sync(0xffffffffu, acc[e], o);
    }

    if (lane == 0) {
        float mx = acc[0];
#pragma unroll
        for (int e = 1; e < NE; e++) mx = fmaxf(mx, acc[e]);
        float p[NE]; float s = 0.f;
#pragma unroll
        for (int e = 0; e < NE; e++) { p[e] = expf(acc[e] - mx); s += p[e]; }
        float inv = 1.f / s;
#pragma unroll
        for (int e = 0; e < NE; e++) p[e] *= inv;

        int e1 = 0;
#pragma unroll
        for (int e = 1; e < NE; e++) if (p[e] > p[e1]) e1 = e;
        int e2 = (e1 == 0) ? 1 : 0;
#pragma unroll
        for (int e = 0; e < NE; e++) if (e != e1 && p[e] > p[e2]) e2 = e;

        float wn = 1.f / (p[e1] + p[e2]);
        g_tok_eid[tok * 2]     = e1;
        g_tok_eid[tok * 2 + 1] = e2;
        g_tok_w[tok * 2]       = p[e1] * wn;
        g_tok_w[tok * 2 + 1]   = p[e2] * wn;
        atomicAdd(&g_cnt[e1], 1);
        atomicAdd(&g_cnt[e2], 1);
#pragma unroll
        for (int e = 0; e < NE; e++) atomicAdd(&s_prob[e], p[e]);
        atomicAdd(&s_frac[e1], 1.f);
        atomicAdd(&s_frac[e2], 1.f);
    }
    __syncthreads();
    if (tid < NE) {
        atomicAdd(&g_probsum[tid], s_prob[tid]);
        atomicAdd(&g_fraccnt[tid], s_frac[tid]);
    }
}

// ---------------------------------------------------------------------------
// K2/K3: scan + fill
// ---------------------------------------------------------------------------
__global__ void scan_kernel() {
    int off = 0;
    for (int e = 0; e < NE; e++) { g_off[e] = off; g_cursor[e] = off; off += g_cnt[e]; }
}

__global__ void fill_kernel() {
    int i = blockIdx.x * blockDim.x + threadIdx.x;
    if (i < NASSIGN) {
        int e = g_tok_eid[i];
        int slot = atomicAdd(&g_cursor[e], 1);
        g_slot_token[slot] = i >> 1;
        g_assign_slot[i]   = slot;
    }
}

// ---------------------------------------------------------------------------
// K4: fused gate/up fp16 GEMM, cp.async 3-stage pipeline, K-slab 64.
//   CTA 128 x (64 gate | 64 up) x 64.  8 warps = 4m x 2n; warp 32x32 on both.
//   Epilogue: h = fp16(silu(g)*u) -> g_hh.
// ---------------------------------------------------------------------------
__global__ void __launch_bounds__(256, 2) gateup_kernel() {
    extern __shared__ __half sm[];
    const int ITERS = DIM / 64;   // 32

    int e   = blockIdx.z;
    int cnt = g_cnt[e];
    int m0  = blockIdx.x * 128;
    if (m0 >= cnt) return;
    int n0  = blockIdx.y * 64;
    int off = g_off[e];

    int tid  = threadIdx.x;
    int lane = tid & 31;
    int w    = tid >> 5;
    int wm   = w & 3;           // 4 m-positions * 32 rows
    int wn   = w >> 2;          // 2 n-positions * 32 cols
    int gid  = lane >> 2;
    int tig  = lane & 3;

    // Loader: thread -> row (tid>>1), half-of-row (tid&1)*32 halves (64B).
    int lrow = tid >> 1;
    int lhf  = (tid & 1) * 32;

    int sidx = off + m0 + lrow;
    if (sidx > NASSIGN - 1) sidx = NASSIGN - 1;
    const __half* aptr = g_xh + (size_t)g_slot_token[sidx] * DIM + lhf;
    const __half* bptr = (lrow < 64)
        ? g_gwh + ((size_t)e * FDIM + n0 + lrow) * DIM + lhf
        : g_uwh + ((size_t)e * FDIM + n0 + (lrow - 64)) * DIM + lhf;

    uint32_t sb = smem_u32(sm);
    uint32_t sa_off  = sb + (uint32_t)(lrow * 144 + (tid & 1) * 64);
    uint32_t sbf_off = sa_off + B_BASE_B2;

    auto issue = [&](int t, int s) {
        uint32_t sa  = sa_off + s * STAGE_B2;
        uint32_t sbb = sbf_off + s * STAGE_B2;
        const __half* ga = aptr + t * 64;
        const __half* gb = bptr + t * 64;
#pragma unroll
        for (int j = 0; j < 4; j++) CP_ASYNC16(sa + j * 16, ga + j * 8);
#pragma unroll
        for (int j = 0; j < 4; j++) CP_ASYNC16(sbb + j * 16, gb + j * 8);
        CP_COMMIT();
    };

    float cg[2][4][4], cu[2][4][4];
#pragma unroll
    for (int mi = 0; mi < 2; mi++)
#pragma unroll
        for (int ni = 0; ni < 4; ni++)
#pragma unroll
            for (int q = 0; q < 4; q++) { cg[mi][ni][q] = 0.f; cu[mi][ni][q] = 0.f; }

    issue(0, 0);
    issue(1, 1);

#pragma unroll 1
    for (int i = 0; i < ITERS; i++) {
        CP_WAIT1();
        __syncthreads();
        if (i + 2 < ITERS) issue(i + 2, (i + 2) % 3); else CP_COMMIT();

        const __half* A = sm + (i % 3) * STAGE_H;
        const __half* B = sm + B_BASE_H + (i % 3) * STAGE_H;
#pragma unroll
        for (int kk = 0; kk < 64; kk += 16) {
            uint32_t a[2][4];
#pragma unroll
            for (int mi = 0; mi < 2; mi++) {
                int r = wm * 32 + mi * 16 + gid;
                a[mi][0] = *(const uint32_t*)&A[r * ROWH + kk + tig * 2];
                a[mi][1] = *(const uint32_t*)&A[(r + 8) * ROWH + kk + tig * 2];
                a[mi][2] = *(const uint32_t*)&A[r * ROWH + kk + tig * 2 + 8];
                a[mi][3] = *(const uint32_t*)&A[(r + 8) * ROWH + kk + tig * 2 + 8];
            }
#pragma unroll
            for (int ni = 0; ni < 4; ni++) {
                int cc = wn * 32 + ni * 8 + gid;
                uint32_t bg0 = *(const uint32_t*)&B[cc * ROWH + kk + tig * 2];
                uint32_t bg1 = *(const uint32_t*)&B[cc * ROWH + kk + tig * 2 + 8];
                uint32_t bu0 = *(const uint32_t*)&B[(cc + 64) * ROWH + kk + tig * 2];
                uint32_t bu1 = *(const uint32_t*)&B[(cc + 64) * ROWH + kk + tig * 2 + 8];
#pragma unroll
                for (int mi = 0; mi < 2; mi++) {
                    mma_f16(cg[mi][ni], a[mi], bg0, bg1);
                    mma_f16(cu[mi][ni], a[mi], bu0, bu1);
                }
            }
        }
        __syncthreads();
    }

    // Epilogue: h = fp16(silu(g) * u)
#pragma unroll
    for (int mi = 0; mi < 2; mi++) {
#pragma unroll
        for (int ni = 0; ni < 4; ni++) {
            int col = n0 + wn * 32 + ni * 8 + 2 * tig;
            int r0  = m0 + wm * 32 + mi * 16 + gid;
            if (r0 < cnt) {
                __half2 h = __floats2half2_rn(silu(cg[mi][ni][0]) * cu[mi][ni][0],
                                              silu(cg[mi][ni][1]) * cu[mi][ni][1]);
                *(__half2*)&g_hh[(size_t)(off + r0) * FDIM + col] = h;
            }
            if (r0 + 8 < cnt) {
                __half2 h = __floats2half2_rn(silu(cg[mi][ni][2]) * cu[mi][ni][2],
                                              silu(cg[mi][ni][3]) * cu[mi][ni][3]);
                *(__half2*)&g_hh[(size_t)(off + r0 + 8) * FDIM + col] = h;
            }
        }
    }
}

// ---------------------------------------------------------------------------
// K5: down fp16 GEMM, cp.async 3-stage pipeline, K-slab 64.
//   CTA 128x128x64, warp 32x64.  Output fp32 to g_tmp.
// ---------------------------------------------------------------------------
__global__ void __launch_bounds__(256, 2) down_kernel() {
    extern __shared__ __half sm[];
    const int ITERS = FDIM / 64;  // 88

    int e   = blockIdx.z;
    int cnt = g_cnt[e];
    int m0  = blockIdx.x * 128;
    if (m0 >= cnt) return;
    int n0  = blockIdx.y * 128;
    int off = g_off[e];

    int tid  = threadIdx.x;
    int lane = tid & 31;
    int w    = tid >> 5;
    int wm   = w & 3;
    int wn   = w >> 2;          // 2 n-positions * 64 cols
    int gid  = lane >> 2;
    int tig  = lane & 3;

    int lrow = tid >> 1;
    int lhf  = (tid & 1) * 32;

    int sidx = off + m0 + lrow;
    if (sidx > NASSIGN - 1) sidx = NASSIGN - 1;
    const __half* aptr = g_hh + (size_t)sidx * FDIM + lhf;
    const __half* bptr = g_dwh + ((size_t)e * DIM + n0 + lrow) * FDIM + lhf;

    uint32_t sb = smem_u32(sm);
    uint32_t sa_off  = sb + (uint32_t)(lrow * 144 + (tid & 1) * 64);
    uint32_t sbf_off = sa_off + B_BASE_B2;

    auto issue = [&](int t, int s) {
        uint32_t sa  = sa_off + s * STAGE_B2;
        uint32_t sbb = sbf_off + s * STAGE_B2;
        const __half* ga = aptr + t * 64;
        const __half* gb = bptr + t * 64;
#pragma unroll
        for (int j = 0; j < 4; j++) CP_ASYNC16(sa + j * 16, ga + j * 8);
#pragma unroll
        for (int j = 0; j < 4; j++) CP_ASYNC16(sbb + j * 16, gb + j * 8);
        CP_COMMIT();
    };

    float c[2][8][4];
#pragma unroll
    for (int mi = 0; mi < 2; mi++)
#pragma unroll
        for (int ni = 0; ni < 8; ni++)
#pragma unroll
            for (int q = 0; q < 4; q++) c[mi][ni][q] = 0.f;

    issue(0, 0);
    issue(1, 1);

#pragma unroll 1
    for (int i = 0; i < ITERS; i++) {
        CP_WAIT1();
        __syncthreads();
        if (i + 2 < ITERS) issue(i + 2, (i + 2) % 3); else CP_COMMIT();

        const __half* A = sm + (i % 3) * STAGE_H;
        const __half* B = sm + B_BASE_H + (i % 3) * STAGE_H;
#pragma unroll
        for (int kk = 0; kk < 64; kk += 16) {
            uint32_t a[2][4];
#pragma unroll
            for (int mi = 0; mi < 2; mi++) {
                int r = wm * 32 + mi * 16 + gid;
                a[mi][0] = *(const uint32_t*)&A[r * ROWH + kk + tig * 2];
                a[mi][1] = *(const uint32_t*)&A[(r + 8) * ROWH + kk + tig * 2];
                a[mi][2] = *(const uint32_t*)&A[r * ROWH + kk + tig * 2 + 8];
                a[mi][3] = *(const uint32_t*)&A[(r + 8) * ROWH + kk + tig * 2 + 8];
            }
#pragma unroll
            for (int ni = 0; ni < 8; ni++) {
                int cc = wn * 64 + ni * 8 + gid;
                uint32_t b0 = *(const uint32_t*)&B[cc * ROWH + kk + tig * 2];
                uint32_t b1 = *(const uint32_t*)&B[cc * ROWH + kk + tig * 2 + 8];
#pragma unroll
                for (int mi = 0; mi < 2; mi++)
                    mma_f16(c[mi][ni], a[mi], b0, b1);
            }
        }
        __syncthreads();
    }

#pragma unroll
    for (int mi = 0; mi < 2; mi++) {
#pragma unroll
        for (int ni = 0; ni < 8; ni++) {
            int col = n0 + wn * 64 + ni * 8 + 2 * tig;
            int r0  = m0 + wm * 32 + mi * 16 + gid;
            if (r0 < cnt)
                *(float2*)&g_tmp[(size_t)(off + r0) * DIM + col] =
                    make_float2(c[mi][ni][0], c[mi][ni][1]);
            if (r0 + 8 < cnt)
                *(float2*)&g_tmp[(size_t)(off + r0 + 8) * DIM + col] =
                    make_float2(c[mi][ni][2], c[mi][ni][3]);
        }
    }
}

// ---------------------------------------------------------------------------
// K6: combine — out[t] = w0*tmp[slot0] + w1*tmp[slot1]
// ---------------------------------------------------------------------------
__global__ void __launch_bounds__(256) combine_kernel(float* __restrict__ out) {
    int t = blockIdx.x;
    int d = blockIdx.y * 1024 + threadIdx.x * 4;
    int s0 = g_assign_slot[2 * t];
    int s1 = g_assign_slot[2 * t + 1];
    float w0 = g_tok_w[2 * t];
    float w1 = g_tok_w[2 * t + 1];
    float4 a = *(const float4*)(g_tmp + (size_t)s0 * DIM + d);
    float4 b = *(const float4*)(g_tmp + (size_t)s1 * DIM + d);
    float4 o;
    o.x = w0 * a.x + w1 * b.x;
    o.y = w0 * a.y + w1 * b.y;
    o.z = w0 * a.z + w1 * b.z;
    o.w = w0 * a.w + w1 * b.w;
    *(float4*)(out + (size_t)t * DIM + d) = o;
}

// ---------------------------------------------------------------------------
// K7: aux loss scalar
// ---------------------------------------------------------------------------
__global__ void aux_kernel(float* o) {
    float a = 0.f;
    for (int e = 0; e < NE; e++)
        a += (g_probsum[e] / (float)NTOK) * (g_fraccnt[e] / (float)NTOK);
    *o = (float)NE * a;
}

// ---------------------------------------------------------------------------
// Entry
// ---------------------------------------------------------------------------
extern "C" void kernel_launch(void* const* d_in, const int* in_sizes, int n_in,
                              void* d_out, int out_size) {
    const float* x  = (const float*)d_in[0];   // [B,T,D]
    const float* rw = (const float*)d_in[1];   // [E,D]
    const float* gw = (const float*)d_in[2];   // [E,F,D]
    const float* uw = (const float*)d_in[3];   // [E,F,D]
    const float* dw = (const float*)d_in[4];   // [E,D,F]
    float* out = (float*)d_out;

    cudaFuncSetAttribute(gateup_kernel, cudaFuncAttributeMaxDynamicSharedMemorySize,
                         SMEM_BYTES);
    cudaFuncSetAttribute(down_kernel, cudaFuncAttributeMaxDynamicSharedMemorySize,
                         SMEM_BYTES);

    reset_kernel<<<1, 32>>>();
    router_kernel<<<NTOK / 8, 256>>>(x, rw);
    scan_kernel<<<1, 1>>>();
    fill_kernel<<<NASSIGN / 256, 256>>>();

    // One-time fp32 -> fp16 conversion of all GEMM operands.
    __half* xh;  cudaGetSymbolAddress((void**)&xh,  g_xh);
    __half* gwh; cudaGetSymbolAddress((void**)&gwh, g_gwh);
    __half* uwh; cudaGetSymbolAddress((void**)&uwh, g_uwh);
    __half* dwh; cudaGetSymbolAddress((void**)&dwh, g_dwh);
    const int WN4 = (NE * FDIM * DIM) / 4;     // 23,068,672
    const int XN4 = (NTOK * DIM) / 4;          //  4,194,304
    cvt_kernel<<<2048, 256>>>(gw, gwh, WN4);
    cvt_kernel<<<2048, 256>>>(uw, uwh, WN4);
    cvt_kernel<<<2048, 256>>>(dw, dwh, WN4);
    cvt_kernel<<<2048, 256>>>(x,  xh,  XN4);

    gateup_kernel<<<dim3(64, FDIM / 64, NE), 256, SMEM_BYTES>>>();
    down_kernel<<<dim3(64, DIM / 128, NE), 256, SMEM_BYTES>>>();
    combine_kernel<<<dim3(NTOK, 2), 256>>>(out);
    if (out_size > NTOK * DIM)
        aux_kernel<<<1, 1>>>(out + (size_t)NTOK * DIM);
}